// round 16
// baseline (speedup 1.0000x reference)
#include <cuda_runtime.h>
#include <cstdint>

// Fixed shapes per reference: B=256, L=512, N=50000
constexpr int B_SZ    = 256;
constexpr int L_SEQ   = 512;
constexpr int N_LOC   = 50000;
constexpr int HSIZE   = 1024;        // hash slots (pow2); worst case 512 keys in one seg
constexpr int NT      = 256;
constexpr int SEGS    = 8;           // CTAs per row; grid = 2048 (proven store geometry)
constexpr int SEG_LEN = 6256;        // 8*6256 = 50048 >= 50000, multiple of 4
constexpr int PAD     = 32;          // 128B padding between per-row flags

// Per-row sync state: ONE int of data (rowmax) + one counter. Zero-initialized.
__device__ int g_rowmax[B_SZ * PAD];
__device__ int g_done  [B_SZ * PAD];

__global__ __launch_bounds__(NT, 8)
void fused_kernel(const int* __restrict__ loc_seq,
                  const int* __restrict__ mask,
                  const float* __restrict__ rw_p,
                  const float* __restrict__ fw_p,
                  float* __restrict__ out)
{
    const int b   = blockIdx.x >> 3;     // batch row
    const int seg = blockIdx.x & 7;      // segment within row
    const int tid = threadIdx.x;

    __shared__ int      h_key[HSIZE];
    __shared__ int      h_cnt[HSIZE];
    __shared__ unsigned h_rec[HSIZE];    // float bits; all values >= 0
    __shared__ int      s_max;           // local max count, later row max broadcast

    const int lo = seg * SEG_LEN;
    const int hi = min(lo + SEG_LEN, N_LOC);
    float* const row = out + (size_t)b * N_LOC;

    // ---- prefetch own row's timesteps into registers (chip idle at t=0) ----
    const int2 lk = reinterpret_cast<const int2*>(loc_seq + (size_t)b * L_SEQ)[tid];
    const int2 mk = reinterpret_cast<const int2*>(mask    + (size_t)b * L_SEQ)[tid];
    const float l2rw = log2f(*rw_p);
    const float fw   = *fw_p;

    // ---- issue the segment zero immediately (the 11-us store engine) ----
    {
        float4* r4 = reinterpret_cast<float4*>(row);
        const float4 z = make_float4(0.f, 0.f, 0.f, 0.f);
        #pragma unroll 4
        for (int i = lo / 4 + tid; i < hi / 4; i += NT)
            r4[i] = z;
    }

    // ---- init hash ----
    #pragma unroll
    for (int i = tid; i < HSIZE; i += NT) {
        h_key[i] = -1;
        h_cnt[i] = 0;
        h_rec[i] = 0u;
    }
    if (tid == 0) s_max = 0;
    __syncthreads();

    // ---- seg-local hash: insert ONLY keys in [lo, hi). Partitioned, not redundant ----
    #pragma unroll
    for (int j = 0; j < 2; j++) {
        const int t   = 2 * tid + j;
        const int key = j ? lk.y : lk.x;
        const int m   = j ? mk.y : mk.x;
        if (key >= lo && key < hi) {
            const float rec = m ? exp2f((float)(L_SEQ - 1 - t) * l2rw) : 0.0f;
            unsigned h = ((unsigned)key * 2654435761u) & (HSIZE - 1);
            for (;;) {
                int cur = h_key[h];
                if (cur == key) break;
                if (cur == -1) {
                    int prev = atomicCAS(&h_key[h], -1, key);
                    if (prev == -1 || prev == key) break;
                }
                h = (h + 1) & (HSIZE - 1);
            }
            atomicAdd(&h_cnt[h], m);
            atomicMax(&h_rec[h], __float_as_uint(rec));
        }
    }
    __syncthreads();

    // ---- local max count reduce ----
    int mf = 0;
    #pragma unroll
    for (int i = tid; i < HSIZE; i += NT) mf = max(mf, h_cnt[i]);
    #pragma unroll
    for (int o = 16; o > 0; o >>= 1) mf = max(mf, __shfl_xor_sync(0xFFFFFFFFu, mf, o));
    if ((tid & 31) == 0) atomicMax(&s_max, mf);
    __syncthreads();

    // ---- single-int cross-CTA exchange: publish local max, count arrivals,
    //      read row max, 16-count reset (replay-safe, unique last consumer) ----
    if (tid == 0) {
        int* const rmp = &g_rowmax[b * PAD];
        int* const dnp = &g_done  [b * PAD];

        if (s_max > 0)
            asm volatile("red.relaxed.gpu.global.max.s32 [%0], %1;"
                         :: "l"(rmp), "r"(s_max) : "memory");
        asm volatile("red.release.gpu.global.add.s32 [%0], %1;"
                     :: "l"(dnp), "r"(1) : "memory");

        // wait for all 8 segments' signals (counter only grows 0..16 this launch)
        int v;
        for (;;) {
            asm volatile("ld.acquire.gpu.global.s32 %0, [%1];"
                         : "=r"(v) : "l"(dnp) : "memory");
            if (v >= SEGS) break;
            __nanosleep(32);
        }
        int rm;
        asm volatile("ld.relaxed.gpu.global.s32 %0, [%1];"
                     : "=r"(rm) : "l"(rmp) : "memory");
        s_max = rm;                       // broadcast row max to the CTA

        int old;
        asm volatile("atom.release.gpu.global.add.s32 %0, [%1], %2;"
                     : "=r"(old) : "l"(dnp), "r"(1) : "memory");
        if (old == 2 * SEGS - 1) {        // last consumer resets both flags to 0
            asm volatile("st.relaxed.gpu.global.s32 [%0], %1;"
                         :: "l"(dnp), "r"(0) : "memory");
            asm volatile("st.relaxed.gpu.global.s32 [%0], %1;"
                         :: "l"(rmp), "r"(0) : "memory");
        }
    }
    __syncthreads();                      // s_max valid; zero stores ordered before scatter

    const float inv = fw / fmaxf((float)s_max, 1.0f);

    // ---- scatter own segment's final values (keys in range by construction) ----
    #pragma unroll
    for (int i = tid; i < HSIZE; i += NT) {
        const int key = h_key[i];
        if (key >= 0) {
            row[key] = __uint_as_float(h_rec[i]) + (float)h_cnt[i] * inv;
        }
    }
}

extern "C" void kernel_launch(void* const* d_in, const int* in_sizes, int n_in,
                              void* d_out, int out_size)
{
    const int*   loc_seq = (const int*)  d_in[0];   // (B, L) int32
    const int*   mask    = (const int*)  d_in[1];   // (B, L) int32
    const float* rw      = (const float*)d_in[2];   // scalar
    const float* fw      = (const float*)d_in[3];   // scalar
    float*       out     = (float*)d_out;           // (B, N) float32

    fused_kernel<<<B_SZ * SEGS, NT>>>(loc_seq, mask, rw, fw, out);
}

// round 17
// speedup vs baseline: 1.1385x; 1.1385x over previous
#include <cuda_runtime.h>
#include <cstdint>

// Fixed shapes per reference: B=256, L=512, N=50000
constexpr int B_SZ   = 256;
constexpr int L_SEQ  = 512;
constexpr int N_LOC  = 50000;
constexpr int HSIZE  = 1024;               // hash slots (pow2), load factor 0.5
constexpr int NT     = 1024;               // one hash slot per thread
constexpr int ROW_F4 = N_LOC / 4;          // 12,500 float4 per row

__global__ __launch_bounds__(NT, 1)
void fused_kernel(const int* __restrict__ loc_seq,
                  const int* __restrict__ mask,
                  const float* __restrict__ rw_p,
                  const float* __restrict__ fw_p,
                  float* __restrict__ out)
{
    const int b   = blockIdx.x;            // one CTA per batch row
    const int tid = threadIdx.x;

    __shared__ int      h_key[HSIZE];
    __shared__ int      h_cnt[HSIZE];
    __shared__ unsigned h_rec[HSIZE];      // float bits; all values >= 0
    __shared__ int      s_maxcnt;

    // ---- start the input loads immediately (in flight during everything below) ----
    int key = -1, m = 0;
    if (tid < L_SEQ) {
        key = loc_seq[(size_t)b * L_SEQ + tid];
        m   = mask   [(size_t)b * L_SEQ + tid];
    }
    const float l2rw = log2f(*rw_p);
    const float fw   = *fw_p;

    // ---- init hash: exactly one slot per thread ----
    h_key[tid] = -1;
    h_cnt[tid] = 0;
    h_rec[tid] = 0u;
    if (tid == 0) s_maxcnt = 0;

    // ---- zero the whole row with STG.128 (ordering-only engine, no completion wait) ----
    float* const row = out + (size_t)b * N_LOC;
    {
        float4* row4 = reinterpret_cast<float4*>(row);
        const float4 z = make_float4(0.f, 0.f, 0.f, 0.f);
        #pragma unroll 4
        for (int i = tid; i < ROW_F4; i += NT)
            row4[i] = z;
    }
    __syncthreads();                       // hash init visible; zeros ordered (cta scope)

    // ---- build the row hash once: 1 insert for each of the 512 timesteps ----
    if (tid < L_SEQ) {
        const float rec = m ? exp2f((float)(L_SEQ - 1 - tid) * l2rw) : 0.0f;
        unsigned h = ((unsigned)key * 2654435761u) & (HSIZE - 1);
        for (;;) {
            int cur = h_key[h];
            if (cur == key) break;
            if (cur == -1) {
                int prev = atomicCAS(&h_key[h], -1, key);
                if (prev == -1 || prev == key) break;
            }
            h = (h + 1) & (HSIZE - 1);
        }
        atomicAdd(&h_cnt[h], m);
        atomicMax(&h_rec[h], __float_as_uint(rec));
    }
    __syncthreads();

    // ---- max frequency: one slot per thread, warp reduce, block combine ----
    int mf = h_cnt[tid];
    #pragma unroll
    for (int o = 16; o > 0; o >>= 1) mf = max(mf, __shfl_xor_sync(0xFFFFFFFFu, mf, o));
    if ((tid & 31) == 0) atomicMax(&s_maxcnt, mf);
    __syncthreads();

    const float inv = fw / fmaxf((float)s_maxcnt, 1.0f);

    // ---- scatter: one slot per thread; ordered after zeros by the barriers above ----
    const int k = h_key[tid];
    if (k >= 0) {
        row[k] = __uint_as_float(h_rec[tid]) + (float)h_cnt[tid] * inv;
    }
}

extern "C" void kernel_launch(void* const* d_in, const int* in_sizes, int n_in,
                              void* d_out, int out_size)
{
    const int*   loc_seq = (const int*)  d_in[0];   // (B, L) int32
    const int*   mask    = (const int*)  d_in[1];   // (B, L) int32
    const float* rw      = (const float*)d_in[2];   // scalar
    const float* fw      = (const float*)d_in[3];   // scalar
    float*       out     = (float*)d_out;           // (B, N) float32

    fused_kernel<<<B_SZ, NT>>>(loc_seq, mask, rw, fw, out);
}